// round 2
// baseline (speedup 1.0000x reference)
#include <cuda_runtime.h>
#include <math.h>

#define N_PTS 32768
typedef unsigned long long u64;

// ---------------- scratch (device globals; no allocations allowed) ----------
__device__ float g_bufA[N_PTS * 256];
__device__ float g_bufB[N_PTS * 256];
__device__ float g_w0[288 * 256];
__device__ float g_w1[2304 * 256];
__device__ float g_w2[2304 * 256];
__device__ float g_w3[2304];

// ---------------- packed f32x2 helpers (sm_103a FFMA2 path) ------------------
__device__ __forceinline__ u64 pack2(float v) {
    u64 r;
    asm("mov.b64 %0, {%1, %1};" : "=l"(r) : "f"(v));
    return r;
}
__device__ __forceinline__ void ffma2(u64& d, u64 a, u64 b) {
    asm("fma.rn.f32x2 %0, %1, %2, %0;" : "+l"(d) : "l"(a), "l"(b));
}

// ---------------- B-spline helpers ------------------------------------------
// knots: arange(-3, 9) * 0.4 + (-1.0), fp32
__device__ __forceinline__ constexpr float kn(int i) {
    return (float)(i - 3) * 0.4f + (-1.0f);
}

// Cubic B-spline bases (8 values) via the reference's Cox-de Boor recurrence.
__device__ __forceinline__ void bspline8(float t, float* bb) {
    float b[11];
#pragma unroll
    for (int i = 0; i < 11; i++)
        b[i] = (t >= kn(i) && t < kn(i + 1)) ? 1.0f : 0.0f;
#pragma unroll
    for (int k = 1; k <= 3; k++) {
#pragma unroll
        for (int i = 0; i < 11 - k; i++) {
            float invdl = 1.0f / (kn(i + k) - kn(i));
            float invdr = 1.0f / (kn(i + k + 1) - kn(i + 1));
            float l = (t - kn(i)) * invdl;
            float r = (kn(i + k + 1) - t) * invdr;
            b[i] = l * b[i] + r * b[i + 1];
        }
    }
#pragma unroll
    for (int i = 0; i < 8; i++) bb[i] = b[i];
}

__device__ __forceinline__ float silu_f(float v) {
    return v * (1.0f / (1.0f + __expf(-v)));
}

// ---------------- weight prep: Wl[k*O + o], k = f*9 + j ---------------------
// j==0 -> bw[o,f]; j in 1..8 -> sw[o,f,j-1] * ss[o,f]
__global__ void prep_w(const float* __restrict__ bw, const float* __restrict__ sw,
                       const float* __restrict__ ss, float* __restrict__ Wl,
                       int F, int O) {
    int idx = blockIdx.x * blockDim.x + threadIdx.x;
    int K = F * 9;
    if (idx >= K * O) return;
    int k = idx / O, o = idx - k * O;
    int f = k / 9, j = k - f * 9;
    float v;
    if (j == 0) v = bw[o * F + f];
    else        v = sw[(o * F + f) * 8 + (j - 1)] * ss[o * F + f];
    Wl[idx] = v;
}

// ---------------- positional encoding ---------------------------------------
__global__ void encode_kernel(const float* __restrict__ x,
                              const float* __restrict__ freq,
                              float* __restrict__ h0) {
    int idx = blockIdx.x * blockDim.x + threadIdx.x;   // N*16 threads
    if (idx >= N_PTS * 16) return;
    int n = idx >> 4, j = idx & 15;
    float enc = x[n] * freq[j];                         // same fp32 rounding as ref
    double ed = (double)enc;
    double q = rint(ed * 0.15915494309189535);          // 1/(2*pi)
    double rd = fma(-q, 6.283185307179586, ed);         // r in [-pi, pi]
    float r = (float)rd;
    float s, c;
    __sincosf(r, &s, &c);                               // accurate on [-pi, pi]
    h0[n * 32 + j] = s;
    h0[n * 32 + 16 + j] = c;
}

// ---------------- fused KAN layer: out(N,256) = A(N,9F) @ W(9F,256) ---------
// TM=64 rows x TN=256 cols per block, 256 threads, 8x8 register microtiles
// held as 8x4 packed f32x2 accumulators (pairs along N). W pairs come free
// from LDS.128; A scalar broadcast packed via mov.b64 {v,v}.
template <int F>
__global__ void __launch_bounds__(256, 2)
kan_layer(const float* __restrict__ hin, const float* __restrict__ W,
          float* __restrict__ hout) {
    constexpr int TM = 64, TN = 256, FC = 4, KC = FC * 9;  // KC = 36
    __shared__ float A_s[KC * TM];   //  9.2 KB, layout [k][row]
    __shared__ float W_s[KC * TN];   // 36.9 KB, layout [k][col]

    const int tid = threadIdx.x;
    const int tx = tid & 31;         // col group: cols tx*8 .. tx*8+7
    const int ty = tid >> 5;         // row group: rows ty*8 .. ty*8+7
    const int row0 = blockIdx.x * TM;
    const int ar = tid & 63;         // A-producer: row
    const int af = tid >> 6;         // A-producer: local feature 0..3

    u64 acc2[8][4];
#pragma unroll
    for (int r = 0; r < 8; r++)
#pragma unroll
        for (int c = 0; c < 4; c++) acc2[r][c] = 0ull;

    for (int f0 = 0; f0 < F; f0 += FC) {
        __syncthreads();
        // -- produce A tile: one (row, feature) pair per thread
        {
            float t = hin[(row0 + ar) * F + f0 + af];
            float bb[8];
            bspline8(t, bb);
            A_s[(af * 9 + 0) * TM + ar] = silu_f(t);
#pragma unroll
            for (int jj = 0; jj < 8; jj++)
                A_s[(af * 9 + 1 + jj) * TM + ar] = bb[jj];
        }
        // -- stage W tile (contiguous KC*TN block), 9 float4 per thread
        {
            const float4* src = reinterpret_cast<const float4*>(W + f0 * 9 * TN);
            float4* dst = reinterpret_cast<float4*>(W_s);
#pragma unroll
            for (int i = 0; i < 9; i++) dst[tid + i * 256] = src[tid + i * 256];
        }
        __syncthreads();
        // -- 8x8 microtile over K chunk, packed-pair FMAs
#pragma unroll 9
        for (int k = 0; k < KC; k++) {
            float a[8];
            *reinterpret_cast<float4*>(a)     = *reinterpret_cast<const float4*>(&A_s[k * TM + ty * 8]);
            *reinterpret_cast<float4*>(a + 4) = *reinterpret_cast<const float4*>(&A_s[k * TM + ty * 8 + 4]);
            ulonglong2 wlo = *reinterpret_cast<const ulonglong2*>(&W_s[k * TN + tx * 8]);
            ulonglong2 whi = *reinterpret_cast<const ulonglong2*>(&W_s[k * TN + tx * 8 + 4]);
#pragma unroll
            for (int r = 0; r < 8; r++) {
                u64 ap = pack2(a[r]);
                ffma2(acc2[r][0], ap, wlo.x);
                ffma2(acc2[r][1], ap, wlo.y);
                ffma2(acc2[r][2], ap, whi.x);
                ffma2(acc2[r][3], ap, whi.y);
            }
        }
    }
    // -- epilogue: coalesced 128-bit stores (pairs are little-endian floats)
#pragma unroll
    for (int r = 0; r < 8; r++) {
        ulonglong2* o = reinterpret_cast<ulonglong2*>(hout + (row0 + ty * 8 + r) * TN + tx * 8);
        o[0] = make_ulonglong2(acc2[r][0], acc2[r][1]);
        o[1] = make_ulonglong2(acc2[r][2], acc2[r][3]);
    }
}

// ---------------- last layer: O = 1 ------------------------------------------
__global__ void kan_last(const float* __restrict__ hin,
                         const float* __restrict__ W,   // 2304 floats
                         float* __restrict__ out) {
    __shared__ float Ws[2304];
    int tid = threadIdx.x;
#pragma unroll
    for (int i = tid; i < 2304; i += 256) Ws[i] = W[i];
    __syncthreads();
    int warp = tid >> 5, lane = tid & 31;
    int n = blockIdx.x * 8 + warp;
    float sum = 0.0f;
#pragma unroll
    for (int ff = 0; ff < 8; ff++) {
        int f = ff * 32 + lane;
        float t = hin[n * 256 + f];
        float bb[8];
        bspline8(t, bb);
        float sl = silu_f(t) * Ws[f * 9];
#pragma unroll
        for (int j = 0; j < 8; j++) sl += bb[j] * Ws[f * 9 + 1 + j];
        sum += sl;
    }
#pragma unroll
    for (int off = 16; off; off >>= 1)
        sum += __shfl_xor_sync(0xffffffffu, sum, off);
    if (lane == 0) out[n] = sum;
}

// ---------------- launch ------------------------------------------------------
extern "C" void kernel_launch(void* const* d_in, const int* in_sizes, int n_in,
                              void* d_out, int out_size) {
    const float* x    = (const float*)d_in[0];
    const float* freq = (const float*)d_in[1];
    const float* bw0  = (const float*)d_in[2];
    const float* sw0  = (const float*)d_in[3];
    const float* ss0  = (const float*)d_in[4];
    const float* bw1  = (const float*)d_in[5];
    const float* sw1  = (const float*)d_in[6];
    const float* ss1  = (const float*)d_in[7];
    const float* bw2  = (const float*)d_in[8];
    const float* sw2  = (const float*)d_in[9];
    const float* ss2  = (const float*)d_in[10];
    const float* bw3  = (const float*)d_in[11];
    const float* sw3  = (const float*)d_in[12];
    const float* ss3  = (const float*)d_in[13];
    float* out = (float*)d_out;

    float *bufA, *bufB, *w0, *w1, *w2, *w3;
    cudaGetSymbolAddress((void**)&bufA, g_bufA);
    cudaGetSymbolAddress((void**)&bufB, g_bufB);
    cudaGetSymbolAddress((void**)&w0, g_w0);
    cudaGetSymbolAddress((void**)&w1, g_w1);
    cudaGetSymbolAddress((void**)&w2, g_w2);
    cudaGetSymbolAddress((void**)&w3, g_w3);

    // weight prep (cheap, fully independent of the activation chain)
    prep_w<<<(288 * 256 + 255) / 256, 256>>>(bw0, sw0, ss0, w0, 32, 256);
    prep_w<<<(2304 * 256 + 255) / 256, 256>>>(bw1, sw1, ss1, w1, 256, 256);
    prep_w<<<(2304 * 256 + 255) / 256, 256>>>(bw2, sw2, ss2, w2, 256, 256);
    prep_w<<<(2304 + 255) / 256, 256>>>(bw3, sw3, ss3, w3, 256, 1);

    encode_kernel<<<(N_PTS * 16) / 256, 256>>>(x, freq, bufA);

    kan_layer<32><<<N_PTS / 64, 256>>>(bufA, w0, bufB);
    kan_layer<256><<<N_PTS / 64, 256>>>(bufB, w1, bufA);
    kan_layer<256><<<N_PTS / 64, 256>>>(bufA, w2, bufB);
    kan_last<<<N_PTS / 8, 256>>>(bufB, w3, out);
}

// round 4
// speedup vs baseline: 2.8409x; 2.8409x over previous
#include <cuda_runtime.h>
#include <cuda_bf16.h>
#include <math.h>
#include <stdint.h>

#define N_PTS 32768
typedef uint32_t u32;

// ---------------- scratch (device globals; no allocations allowed) ----------
__device__ float g_bufA[N_PTS * 256];
__device__ float g_bufB[N_PTS * 256];
__device__ __align__(16) __nv_bfloat16 g_W0h[256 * 288],  g_W0l[256 * 288];
__device__ __align__(16) __nv_bfloat16 g_W1h[256 * 2304], g_W1l[256 * 2304];
__device__ __align__(16) __nv_bfloat16 g_W2h[256 * 2304], g_W2l[256 * 2304];
__device__ float g_w3[2304];

// ---------------- PTX helpers (compute_80-era, arch-neutral) -----------------
__device__ __forceinline__ u32 smem_u32(const void* p) {
    u32 a;
    asm("{ .reg .u64 t; cvta.to.shared.u64 t, %1; cvt.u32.u64 %0, t; }"
        : "=r"(a) : "l"(p));
    return a;
}
__device__ __forceinline__ void ldsm_x4(u32* r, u32 addr) {
    asm volatile("ldmatrix.sync.aligned.m8n8.x4.shared.b16 {%0,%1,%2,%3}, [%4];"
                 : "=r"(r[0]), "=r"(r[1]), "=r"(r[2]), "=r"(r[3]) : "r"(addr));
}
__device__ __forceinline__ void mma_bf16(float* c, const u32* a, const u32* b) {
    asm volatile(
        "mma.sync.aligned.m16n8k16.row.col.f32.bf16.bf16.f32 "
        "{%0,%1,%2,%3}, {%4,%5,%6,%7}, {%8,%9}, {%0,%1,%2,%3};"
        : "+f"(c[0]), "+f"(c[1]), "+f"(c[2]), "+f"(c[3])
        : "r"(a[0]), "r"(a[1]), "r"(a[2]), "r"(a[3]), "r"(b[0]), "r"(b[1]));
}

// ---------------- B-spline / silu -------------------------------------------
__device__ __forceinline__ constexpr float kn(int i) {
    return (float)(i - 3) * 0.4f + (-1.0f);
}
__device__ __forceinline__ void bspline8(float t, float* bb) {
    float b[11];
#pragma unroll
    for (int i = 0; i < 11; i++)
        b[i] = (t >= kn(i) && t < kn(i + 1)) ? 1.0f : 0.0f;
#pragma unroll
    for (int k = 1; k <= 3; k++) {
#pragma unroll
        for (int i = 0; i < 11 - k; i++) {
            float invdl = 1.0f / (kn(i + k) - kn(i));
            float invdr = 1.0f / (kn(i + k + 1) - kn(i + 1));
            float l = (t - kn(i)) * invdl;
            float r = (kn(i + k + 1) - t) * invdr;
            b[i] = l * b[i] + r * b[i + 1];
        }
    }
#pragma unroll
    for (int i = 0; i < 8; i++) bb[i] = b[i];
}
__device__ __forceinline__ float silu_f(float v) {
    return v * (1.0f / (1.0f + __expf(-v)));
}

// ---------------- weight prep: Wh/Wl[o*K + k], k = f*9 + j ------------------
__global__ void prep_w_bf16(const float* __restrict__ bw, const float* __restrict__ sw,
                            const float* __restrict__ ss,
                            __nv_bfloat16* __restrict__ Wh, __nv_bfloat16* __restrict__ Wl,
                            int F) {
    int K = 9 * F;
    int idx = blockIdx.x * blockDim.x + threadIdx.x;
    if (idx >= 256 * K) return;
    int o = idx / K, k = idx - o * K;
    int f = k / 9, j = k - f * 9;
    float v = (j == 0) ? bw[o * F + f] : sw[(o * F + f) * 8 + (j - 1)] * ss[o * F + f];
    __nv_bfloat16 hi = __float2bfloat16(v);
    Wh[idx] = hi;
    Wl[idx] = __float2bfloat16(v - __bfloat162float(hi));
}
__global__ void prep_w3(const float* __restrict__ bw, const float* __restrict__ sw,
                        const float* __restrict__ ss, float* __restrict__ Wl) {
    int k = blockIdx.x * blockDim.x + threadIdx.x;
    if (k >= 2304) return;
    int f = k / 9, j = k - f * 9;
    Wl[k] = (j == 0) ? bw[f] : sw[f * 8 + (j - 1)] * ss[f];
}

// ---------------- positional encoding ---------------------------------------
__global__ void encode_kernel(const float* __restrict__ x,
                              const float* __restrict__ freq,
                              float* __restrict__ h0) {
    int idx = blockIdx.x * blockDim.x + threadIdx.x;
    if (idx >= N_PTS * 16) return;
    int n = idx >> 4, j = idx & 15;
    float enc = x[n] * freq[j];
    double ed = (double)enc;
    double q = rint(ed * 0.15915494309189535);
    double rd = fma(-q, 6.283185307179586, ed);
    float r = (float)rd;
    float s, c;
    __sincosf(r, &s, &c);
    h0[n * 32 + j] = s;
    h0[n * 32 + 16 + j] = c;
}

// ---------------- fused HMMA KAN layer ---------------------------------------
// C(128 rows x 128 cols per CTA) = A(.,9F) @ W(256,9F)^T, 3-way bf16 split.
// K chunks of 144 (16 features); A produced in-kernel (silu + splines).
// smem tiles 128 x 152 bf16 (stride 304B, conflict-free ldmatrix).
template <int F>
__global__ void __launch_bounds__(256, 1)
kan_hmma(const float* __restrict__ hin,
         const __nv_bfloat16* __restrict__ Wh, const __nv_bfloat16* __restrict__ Wl,
         float* __restrict__ out) {
    constexpr int K = 9 * F, NCH = K / 144, LDS_ = 152;
    constexpr u32 TILE = 128 * LDS_ * 2;         // 38912 B
    extern __shared__ __align__(16) char smem[];
    __nv_bfloat16* sAh = reinterpret_cast<__nv_bfloat16*>(smem);
    __nv_bfloat16* sAl = reinterpret_cast<__nv_bfloat16*>(smem + TILE);
    __nv_bfloat16* sWh = reinterpret_cast<__nv_bfloat16*>(smem + 2 * TILE);
    __nv_bfloat16* sWl = reinterpret_cast<__nv_bfloat16*>(smem + 3 * TILE);
    const u32 sbase = smem_u32(smem);

    const int tid = threadIdx.x;
    const int lane = tid & 31, warp = tid >> 5;
    const int wm = (warp & 3) * 32;              // warp m-offset (4 warps)
    const int wn = (warp >> 2) * 64;             // warp n-offset (2 warps)
    const int row0 = blockIdx.x * 128;
    const int n0 = blockIdx.y * 128;

    // ldmatrix byte-address bases (k advances by 32B per k16 step)
    u32 aAddr[2], bAddr[4];
#pragma unroll
    for (int mi = 0; mi < 2; mi++)
        aAddr[mi] = (u32)((wm + mi * 16 + (lane & 15)) * (LDS_ * 2) + (lane >> 4) * 16);
#pragma unroll
    for (int jj = 0; jj < 4; jj++)
        bAddr[jj] = (u32)((wn + jj * 16 + (lane & 7) + ((lane >> 4) << 3)) * (LDS_ * 2)
                          + (((lane >> 3) & 1) << 4));

    float acc[2][8][4];
#pragma unroll
    for (int mi = 0; mi < 2; mi++)
#pragma unroll
        for (int nf = 0; nf < 8; nf++)
#pragma unroll
            for (int q = 0; q < 4; q++) acc[mi][nf][q] = 0.0f;

    for (int c = 0; c < NCH; c++) {
        __syncthreads();
        // ---- produce A chunk: 128 rows x 16 features -> K 0..143 (hi/lo)
#pragma unroll
        for (int i = 0; i < 8; i++) {
            int id = tid + 256 * i;
            int f = id & 15, row = id >> 4;          // lanes: consecutive f, coalesced-ish
            float t = hin[(size_t)(row0 + row) * F + c * 16 + f];
            float v[9];
            v[0] = silu_f(t);
            bspline8(t, v + 1);
            int kb = row * LDS_ + f * 9;
#pragma unroll
            for (int j = 0; j < 9; j++) {
                __nv_bfloat16 hi = __float2bfloat16(v[j]);
                sAh[kb + j] = hi;
                sAl[kb + j] = __float2bfloat16(v[j] - __bfloat162float(hi));
            }
        }
        // ---- load W chunk: rows n0..n0+127, K c*144..+143 (18 uint4/row)
#pragma unroll
        for (int i = 0; i < 9; i++) {
            int u = tid + 256 * i;
            int row = u / 18, pos = u - row * 18;
            size_t gi = ((size_t)(n0 + row) * K + c * 144) / 8 + pos;
            u32 so = (u32)(row * LDS_ + pos * 8);
            *reinterpret_cast<uint4*>(sWh + so) = reinterpret_cast<const uint4*>(Wh)[gi];
            *reinterpret_cast<uint4*>(sWl + so) = reinterpret_cast<const uint4*>(Wl)[gi];
        }
        __syncthreads();
        // ---- 9 k16 steps of 3-way-split mma
#pragma unroll 3
        for (int ks = 0; ks < 9; ks++) {
            const u32 ko = (u32)(ks * 32);
            u32 ah[2][4], al[2][4], bh[4][4], bl[4][4];
#pragma unroll
            for (int mi = 0; mi < 2; mi++) {
                ldsm_x4(ah[mi], sbase + aAddr[mi] + ko);
                ldsm_x4(al[mi], sbase + TILE + aAddr[mi] + ko);
            }
#pragma unroll
            for (int jj = 0; jj < 4; jj++) {
                ldsm_x4(bh[jj], sbase + 2 * TILE + bAddr[jj] + ko);
                ldsm_x4(bl[jj], sbase + 3 * TILE + bAddr[jj] + ko);
            }
#pragma unroll
            for (int mi = 0; mi < 2; mi++)
#pragma unroll
                for (int nf = 0; nf < 8; nf++) {
                    const u32* Bh = &bh[nf >> 1][(nf & 1) * 2];
                    const u32* Bl = &bl[nf >> 1][(nf & 1) * 2];
                    mma_bf16(acc[mi][nf], ah[mi], Bh);
                    mma_bf16(acc[mi][nf], ah[mi], Bl);
                    mma_bf16(acc[mi][nf], al[mi], Bh);
                }
        }
    }
    // ---- epilogue: c-frag direct stores (float2 per frag-half)
#pragma unroll
    for (int mi = 0; mi < 2; mi++)
#pragma unroll
        for (int nf = 0; nf < 8; nf++) {
            int r0 = row0 + wm + mi * 16 + (lane >> 2);
            int cc = n0 + wn + nf * 8 + (lane & 3) * 2;
            *reinterpret_cast<float2*>(&out[(size_t)r0 * 256 + cc]) =
                make_float2(acc[mi][nf][0], acc[mi][nf][1]);
            *reinterpret_cast<float2*>(&out[(size_t)(r0 + 8) * 256 + cc]) =
                make_float2(acc[mi][nf][2], acc[mi][nf][3]);
        }
}

// ---------------- last layer: O = 1 ------------------------------------------
__global__ void kan_last(const float* __restrict__ hin,
                         const float* __restrict__ W,
                         float* __restrict__ out) {
    __shared__ float Ws[2304];
    int tid = threadIdx.x;
#pragma unroll
    for (int i = tid; i < 2304; i += 256) Ws[i] = W[i];
    __syncthreads();
    int warp = tid >> 5, lane = tid & 31;
    int n = blockIdx.x * 8 + warp;
    float sum = 0.0f;
#pragma unroll
    for (int ff = 0; ff < 8; ff++) {
        int f = ff * 32 + lane;
        float t = hin[n * 256 + f];
        float bb[8];
        bspline8(t, bb);
        float sl = silu_f(t) * Ws[f * 9];
#pragma unroll
        for (int j = 0; j < 8; j++) sl += bb[j] * Ws[f * 9 + 1 + j];
        sum += sl;
    }
#pragma unroll
    for (int off = 16; off; off >>= 1)
        sum += __shfl_xor_sync(0xffffffffu, sum, off);
    if (lane == 0) out[n] = sum;
}

// ---------------- launch ------------------------------------------------------
extern "C" void kernel_launch(void* const* d_in, const int* in_sizes, int n_in,
                              void* d_out, int out_size) {
    const float* x    = (const float*)d_in[0];
    const float* freq = (const float*)d_in[1];
    const float* bw0  = (const float*)d_in[2];
    const float* sw0  = (const float*)d_in[3];
    const float* ss0  = (const float*)d_in[4];
    const float* bw1  = (const float*)d_in[5];
    const float* sw1  = (const float*)d_in[6];
    const float* ss1  = (const float*)d_in[7];
    const float* bw2  = (const float*)d_in[8];
    const float* sw2  = (const float*)d_in[9];
    const float* ss2  = (const float*)d_in[10];
    const float* bw3  = (const float*)d_in[11];
    const float* sw3  = (const float*)d_in[12];
    const float* ss3  = (const float*)d_in[13];
    float* out = (float*)d_out;

    float *bufA, *bufB, *w3;
    __nv_bfloat16 *W0h, *W0l, *W1h, *W1l, *W2h, *W2l;
    cudaGetSymbolAddress((void**)&bufA, g_bufA);
    cudaGetSymbolAddress((void**)&bufB, g_bufB);
    cudaGetSymbolAddress((void**)&W0h, g_W0h);
    cudaGetSymbolAddress((void**)&W0l, g_W0l);
    cudaGetSymbolAddress((void**)&W1h, g_W1h);
    cudaGetSymbolAddress((void**)&W1l, g_W1l);
    cudaGetSymbolAddress((void**)&W2h, g_W2h);
    cudaGetSymbolAddress((void**)&W2l, g_W2l);
    cudaGetSymbolAddress((void**)&w3, g_w3);

    const int SMEM = 4 * 128 * 152 * 2;   // 155648 B
    cudaFuncSetAttribute(kan_hmma<32>,  cudaFuncAttributeMaxDynamicSharedMemorySize, SMEM);
    cudaFuncSetAttribute(kan_hmma<256>, cudaFuncAttributeMaxDynamicSharedMemorySize, SMEM);

    prep_w_bf16<<<(256 * 288 + 255) / 256, 256>>>(bw0, sw0, ss0, W0h, W0l, 32);
    prep_w_bf16<<<(256 * 2304 + 255) / 256, 256>>>(bw1, sw1, ss1, W1h, W1l, 256);
    prep_w_bf16<<<(256 * 2304 + 255) / 256, 256>>>(bw2, sw2, ss2, W2h, W2l, 256);
    prep_w3<<<9, 256>>>(bw3, sw3, ss3, w3);

    encode_kernel<<<(N_PTS * 16) / 256, 256>>>(x, freq, bufA);

    dim3 grid(N_PTS / 128, 2);
    kan_hmma<32><<<grid, 256, SMEM>>>(bufA, W0h, W0l, bufB);
    kan_hmma<256><<<grid, 256, SMEM>>>(bufB, W1h, W1l, bufA);
    kan_hmma<256><<<grid, 256, SMEM>>>(bufA, W2h, W2l, bufB);
    kan_last<<<N_PTS / 8, 256>>>(bufB, w3, out);
}

// round 5
// speedup vs baseline: 2.8510x; 1.0035x over previous
#include <cuda_runtime.h>
#include <cuda_bf16.h>
#include <math.h>
#include <stdint.h>

#define N_PTS 32768
typedef uint32_t u32;

// ---------------- scratch (device globals; no allocations allowed) ----------
__device__ float g_bufA[N_PTS * 256];
__device__ float g_bufB[N_PTS * 256];
__device__ __align__(16) __nv_bfloat16 g_W0h[256 * 288],  g_W0l[256 * 288];
__device__ __align__(16) __nv_bfloat16 g_W1h[256 * 2304], g_W1l[256 * 2304];
__device__ __align__(16) __nv_bfloat16 g_W2h[256 * 2304], g_W2l[256 * 2304];
__device__ float g_w3[2304];

// ---------------- PTX helpers (compute_80-era, arch-neutral) -----------------
__device__ __forceinline__ u32 smem_u32(const void* p) {
    u32 a;
    asm("{ .reg .u64 t; cvta.to.shared.u64 t, %1; cvt.u32.u64 %0, t; }"
        : "=r"(a) : "l"(p));
    return a;
}
__device__ __forceinline__ void ldsm_x4(u32* r, u32 addr) {
    asm volatile("ldmatrix.sync.aligned.m8n8.x4.shared.b16 {%0,%1,%2,%3}, [%4];"
                 : "=r"(r[0]), "=r"(r[1]), "=r"(r[2]), "=r"(r[3]) : "r"(addr));
}
__device__ __forceinline__ void mma_bf16(float* c, const u32* a, const u32* b) {
    asm volatile(
        "mma.sync.aligned.m16n8k16.row.col.f32.bf16.bf16.f32 "
        "{%0,%1,%2,%3}, {%4,%5,%6,%7}, {%8,%9}, {%0,%1,%2,%3};"
        : "+f"(c[0]), "+f"(c[1]), "+f"(c[2]), "+f"(c[3])
        : "r"(a[0]), "r"(a[1]), "r"(a[2]), "r"(a[3]), "r"(b[0]), "r"(b[1]));
}

// ---------------- B-spline / silu -------------------------------------------
__device__ __forceinline__ constexpr float kn(int i) {
    return (float)(i - 3) * 0.4f + (-1.0f);
}
__device__ __forceinline__ void bspline8(float t, float* bb) {
    float b[11];
#pragma unroll
    for (int i = 0; i < 11; i++)
        b[i] = (t >= kn(i) && t < kn(i + 1)) ? 1.0f : 0.0f;
#pragma unroll
    for (int k = 1; k <= 3; k++) {
#pragma unroll
        for (int i = 0; i < 11 - k; i++) {
            float invdl = 1.0f / (kn(i + k) - kn(i));
            float invdr = 1.0f / (kn(i + k + 1) - kn(i + 1));
            float l = (t - kn(i)) * invdl;
            float r = (kn(i + k + 1) - t) * invdr;
            b[i] = l * b[i] + r * b[i + 1];
        }
    }
#pragma unroll
    for (int i = 0; i < 8; i++) bb[i] = b[i];
}
__device__ __forceinline__ float silu_f(float v) {
    return v * (1.0f / (1.0f + __expf(-v)));
}

// ---------------- fused weight prep (single launch) --------------------------
// segments: [0,288) W0 | [288,2592) W1 | [2592,4896) W2 | [4896,4905) w3
__device__ __forceinline__ void prep_one(const float* bw, const float* sw,
                                         const float* ss,
                                         __nv_bfloat16* Wh, __nv_bfloat16* Wl,
                                         int F, int idx) {
    int K = 9 * F;
    if (idx >= 256 * K) return;
    int o = idx / K, k = idx - o * K;
    int f = k / 9, j = k - f * 9;
    float v = (j == 0) ? bw[o * F + f] : sw[(o * F + f) * 8 + (j - 1)] * ss[o * F + f];
    __nv_bfloat16 hi = __float2bfloat16(v);
    Wh[idx] = hi;
    Wl[idx] = __float2bfloat16(v - __bfloat162float(hi));
}
__global__ void prep_all(const float* __restrict__ bw0, const float* __restrict__ sw0, const float* __restrict__ ss0,
                         const float* __restrict__ bw1, const float* __restrict__ sw1, const float* __restrict__ ss1,
                         const float* __restrict__ bw2, const float* __restrict__ sw2, const float* __restrict__ ss2,
                         const float* __restrict__ bw3, const float* __restrict__ sw3, const float* __restrict__ ss3,
                         __nv_bfloat16* __restrict__ W0h, __nv_bfloat16* __restrict__ W0l,
                         __nv_bfloat16* __restrict__ W1h, __nv_bfloat16* __restrict__ W1l,
                         __nv_bfloat16* __restrict__ W2h, __nv_bfloat16* __restrict__ W2l,
                         float* __restrict__ w3) {
    int b = blockIdx.x, t = threadIdx.x;
    if (b < 288) {
        prep_one(bw0, sw0, ss0, W0h, W0l, 32, b * 256 + t);
    } else if (b < 2592) {
        prep_one(bw1, sw1, ss1, W1h, W1l, 256, (b - 288) * 256 + t);
    } else if (b < 4896) {
        prep_one(bw2, sw2, ss2, W2h, W2l, 256, (b - 2592) * 256 + t);
    } else {
        int k = (b - 4896) * 256 + t;
        if (k < 2304) {
            int f = k / 9, j = k - f * 9;
            w3[k] = (j == 0) ? bw3[f] : sw3[f * 8 + (j - 1)] * ss3[f];
        }
    }
}

// ---------------- positional encoding ---------------------------------------
__global__ void encode_kernel(const float* __restrict__ x,
                              const float* __restrict__ freq,
                              float* __restrict__ h0) {
    int idx = blockIdx.x * blockDim.x + threadIdx.x;
    if (idx >= N_PTS * 16) return;
    int n = idx >> 4, j = idx & 15;
    float enc = x[n] * freq[j];
    double ed = (double)enc;
    double q = rint(ed * 0.15915494309189535);
    double rd = fma(-q, 6.283185307179586, ed);
    float r = (float)rd;
    float s, c;
    __sincosf(r, &s, &c);
    h0[n * 32 + j] = s;
    h0[n * 32 + 16 + j] = c;
}

// ---------------- smem swizzle: row stride 288 B (18 x 16B units) ------------
// phys byte offset for (row, 16B-unit u): u<16 -> row*288 + ((u*16) ^ ((row&7)*16))
//                                         u>=16 -> row*288 + 256 + (((u^row)&1)*16)
__device__ __forceinline__ u32 swz_off(int row, int u) {
    if (u < 16) return (u32)(row * 288 + ((u * 16) ^ ((row & 7) * 16)));
    return (u32)(row * 288 + 256 + (((u ^ row) & 1) * 16));
}

// ---------------- fused HMMA KAN layer ---------------------------------------
// CTA tile: 64 rows x 128 cols, K chunks of 144 (16 features), 3-way bf16 split.
// smem: Ah(18432) | Al(18432) | Wh(36864) | Wl(36864) = 110592 B -> 2 CTAs/SM.
template <int F>
__global__ void __launch_bounds__(256, 2)
kan_hmma(const float* __restrict__ hin,
         const __nv_bfloat16* __restrict__ Wh, const __nv_bfloat16* __restrict__ Wl,
         float* __restrict__ out) {
    constexpr int K = 9 * F, NCH = K / 144;
    constexpr u32 AH = 0, AL = 18432, WH = 36864, WL = 73728;
    extern __shared__ __align__(16) char smem[];
    __nv_bfloat16* sm = reinterpret_cast<__nv_bfloat16*>(smem);
    const u32 sbase = smem_u32(smem);

    const int tid = threadIdx.x;
    const int lane = tid & 31, warp = tid >> 5;
    const int wm = (warp & 1) * 32;              // 2 m-groups of 32
    const int wn = (warp >> 1) * 32;             // 4 n-groups of 32
    const int row0 = blockIdx.x * 64;
    const int n0 = blockIdx.y * 128;

    // per-thread ldmatrix row bases
    int rowA[2], rowB[2];
    const int bitA = lane >> 4;                  // unit parity within k16 step
    const int bitB = (lane >> 3) & 1;
#pragma unroll
    for (int mi = 0; mi < 2; mi++) rowA[mi] = wm + mi * 16 + (lane & 15);
#pragma unroll
    for (int jj = 0; jj < 2; jj++) rowB[jj] = wn + jj * 16 + (lane & 7) + ((lane >> 4) << 3);

    float acc[2][4][4];
#pragma unroll
    for (int mi = 0; mi < 2; mi++)
#pragma unroll
        for (int nf = 0; nf < 4; nf++)
#pragma unroll
            for (int q = 0; q < 4; q++) acc[mi][nf][q] = 0.0f;

    for (int c = 0; c < NCH; c++) {
        __syncthreads();
        // ---- produce A chunk: 64 rows x 16 features (hi/lo), swizzled
#pragma unroll
        for (int i = 0; i < 4; i++) {
            int id = tid + 256 * i;
            int f = id & 15, row = id >> 4;      // row 0..63
            float t = hin[(size_t)(row0 + row) * F + c * 16 + f];
            float v[9];
            v[0] = silu_f(t);
            bspline8(t, v + 1);
#pragma unroll
            for (int j = 0; j < 9; j++) {
                int k = f * 9 + j;
                u32 off = swz_off(row, k >> 3) + (k & 7) * 2;
                __nv_bfloat16 hi = __float2bfloat16(v[j]);
                *reinterpret_cast<__nv_bfloat16*>(smem + AH + off) = hi;
                *reinterpret_cast<__nv_bfloat16*>(smem + AL + off) =
                    __float2bfloat16(v[j] - __bfloat162float(hi));
            }
        }
        // ---- load W chunk: 128 rows x 18 uint4 (hi/lo), swizzled
#pragma unroll
        for (int i = 0; i < 9; i++) {
            int u = tid + 256 * i;
            int row = u / 18, pos = u - row * 18;
            size_t gi = ((size_t)(n0 + row) * K + c * 144) / 8 + pos;
            u32 off = swz_off(row, pos);
            *reinterpret_cast<uint4*>(smem + WH + off) = reinterpret_cast<const uint4*>(Wh)[gi];
            *reinterpret_cast<uint4*>(smem + WL + off) = reinterpret_cast<const uint4*>(Wl)[gi];
        }
        __syncthreads();
        // ---- 9 k16 steps of 3-way-split mma
#pragma unroll
        for (int ks = 0; ks < 9; ks++) {
            u32 ah[2][4], al[2][4], bh[2][4], bl[2][4];
#pragma unroll
            for (int mi = 0; mi < 2; mi++) {
                u32 off = swz_off(rowA[mi], 2 * ks + bitA);
                ldsm_x4(ah[mi], sbase + AH + off);
                ldsm_x4(al[mi], sbase + AL + off);
            }
#pragma unroll
            for (int jj = 0; jj < 2; jj++) {
                u32 off = swz_off(rowB[jj], 2 * ks + bitB);
                ldsm_x4(bh[jj], sbase + WH + off);
                ldsm_x4(bl[jj], sbase + WL + off);
            }
#pragma unroll
            for (int mi = 0; mi < 2; mi++)
#pragma unroll
                for (int nf = 0; nf < 4; nf++) {
                    const u32* Bh = &bh[nf >> 1][(nf & 1) * 2];
                    const u32* Bl = &bl[nf >> 1][(nf & 1) * 2];
                    mma_bf16(acc[mi][nf], ah[mi], Bh);
                    mma_bf16(acc[mi][nf], ah[mi], Bl);
                    mma_bf16(acc[mi][nf], al[mi], Bh);
                }
        }
    }
    // ---- epilogue: c-frag direct stores
#pragma unroll
    for (int mi = 0; mi < 2; mi++)
#pragma unroll
        for (int nf = 0; nf < 4; nf++) {
            int r0 = row0 + wm + mi * 16 + (lane >> 2);
            int cc = n0 + wn + nf * 8 + (lane & 3) * 2;
            *reinterpret_cast<float2*>(&out[(size_t)r0 * 256 + cc]) =
                make_float2(acc[mi][nf][0], acc[mi][nf][1]);
            *reinterpret_cast<float2*>(&out[(size_t)(r0 + 8) * 256 + cc]) =
                make_float2(acc[mi][nf][2], acc[mi][nf][3]);
        }
}

// ---------------- last layer: O = 1 ------------------------------------------
__global__ void kan_last(const float* __restrict__ hin,
                         const float* __restrict__ W,
                         float* __restrict__ out) {
    __shared__ float Ws[2304];
    int tid = threadIdx.x;
#pragma unroll
    for (int i = tid; i < 2304; i += 256) Ws[i] = W[i];
    __syncthreads();
    int warp = tid >> 5, lane = tid & 31;
    int n = blockIdx.x * 8 + warp;
    float sum = 0.0f;
#pragma unroll
    for (int ff = 0; ff < 8; ff++) {
        int f = ff * 32 + lane;
        float t = hin[n * 256 + f];
        float bb[8];
        bspline8(t, bb);
        float sl = silu_f(t) * Ws[f * 9];
#pragma unroll
        for (int j = 0; j < 8; j++) sl += bb[j] * Ws[f * 9 + 1 + j];
        sum += sl;
    }
#pragma unroll
    for (int off = 16; off; off >>= 1)
        sum += __shfl_xor_sync(0xffffffffu, sum, off);
    if (lane == 0) out[n] = sum;
}

// ---------------- launch ------------------------------------------------------
extern "C" void kernel_launch(void* const* d_in, const int* in_sizes, int n_in,
                              void* d_out, int out_size) {
    const float* x    = (const float*)d_in[0];
    const float* freq = (const float*)d_in[1];
    const float* bw0  = (const float*)d_in[2];
    const float* sw0  = (const float*)d_in[3];
    const float* ss0  = (const float*)d_in[4];
    const float* bw1  = (const float*)d_in[5];
    const float* sw1  = (const float*)d_in[6];
    const float* ss1  = (const float*)d_in[7];
    const float* bw2  = (const float*)d_in[8];
    const float* sw2  = (const float*)d_in[9];
    const float* ss2  = (const float*)d_in[10];
    const float* bw3  = (const float*)d_in[11];
    const float* sw3  = (const float*)d_in[12];
    const float* ss3  = (const float*)d_in[13];
    float* out = (float*)d_out;

    float *bufA, *bufB, *w3;
    __nv_bfloat16 *W0h, *W0l, *W1h, *W1l, *W2h, *W2l;
    cudaGetSymbolAddress((void**)&bufA, g_bufA);
    cudaGetSymbolAddress((void**)&bufB, g_bufB);
    cudaGetSymbolAddress((void**)&W0h, g_W0h);
    cudaGetSymbolAddress((void**)&W0l, g_W0l);
    cudaGetSymbolAddress((void**)&W1h, g_W1h);
    cudaGetSymbolAddress((void**)&W1l, g_W1l);
    cudaGetSymbolAddress((void**)&W2h, g_W2h);
    cudaGetSymbolAddress((void**)&W2l, g_W2l);
    cudaGetSymbolAddress((void**)&w3, g_w3);

    const int SMEM = 110592;
    cudaFuncSetAttribute(kan_hmma<32>,  cudaFuncAttributeMaxDynamicSharedMemorySize, SMEM);
    cudaFuncSetAttribute(kan_hmma<256>, cudaFuncAttributeMaxDynamicSharedMemorySize, SMEM);

    // [0] all weight prep in one launch
    prep_all<<<4905, 256>>>(bw0, sw0, ss0, bw1, sw1, ss1, bw2, sw2, ss2,
                            bw3, sw3, ss3, W0h, W0l, W1h, W1l, W2h, W2l, w3);
    // [1] encoding
    encode_kernel<<<(N_PTS * 16) / 256, 256>>>(x, freq, bufA);

    dim3 grid(N_PTS / 64, 2);
    // [2] layer 0
    kan_hmma<32><<<grid, 256, SMEM>>>(bufA, W0h, W0l, bufB);
    // [3] layer 1  (<- ncu capture slot)
    kan_hmma<256><<<grid, 256, SMEM>>>(bufB, W1h, W1l, bufA);
    // [4] layer 2
    kan_hmma<256><<<grid, 256, SMEM>>>(bufA, W2h, W2l, bufB);
    // [5] last layer
    kan_last<<<N_PTS / 8, 256>>>(bufB, w3, out);
}